// round 7
// baseline (speedup 1.0000x reference)
#include <cuda_runtime.h>
#include <cuda_bf16.h>
#include <mma.h>
using namespace nvcuda;

#define NN 512
#define RST 516

// ---------------- device scratch (no allocations allowed) ----------------
__device__ __align__(16) float2 g_slot[2 * 512 * 512];   // 4 MB
__device__ float g_U [NN * NN];
__device__ float g_Vs[NN * NN];
__device__ float g_W [NN * NN];

// ---------------- 1) cos/sin precompute into padded slots ----------------
__global__ void setup_cs_kernel(const float* __restrict__ phiU,
                                const float* __restrict__ phiV) {
    int tid = blockIdx.x * blockDim.x + threadIdx.x;
    if (tid >= 2 * 512 * 512) return;
    int mat = tid >> 18;
    int r   = tid & 262143;
    int i   = r >> 9;
    int m   = r & 511;
    float c = 1.0f, s = 0.0f;
    if (m < 511 - i) {
        int k = i * 511 - (i * (i - 1)) / 2 + m;
        float ph = mat ? __ldg(&phiV[k]) : __ldg(&phiU[k]);
        sincosf(ph, &s, &c);
    }
    g_slot[tid] = make_float2(c, s);
}

// ---------------- 2) Givens-mesh reconstruction, 8-warp chain-split ----------------
#define P2STEP(u, cc, ss) do { float _t2 = (cc)*(u); float _t1 = (ss)*(u); \
                               (u) = fmaf((ss), A, _t2); A = fmaf((cc), A, -_t1); } while (0)
#define P1STEP(u, cc, ss) do { Dw = fmaf((cc), Dw, (ss)*(u)); Cw = (cc)*Cw; } while (0)

__global__ void __launch_bounds__(256) reconstruct_kernel(const float* __restrict__ dU,
                                                          const float* __restrict__ dV,
                                                          const float* __restrict__ sigma) {
    extern __shared__ float sm[];
    float*  cols  = sm;
    float2* ring0 = (float2*)(sm + 32 * RST);
    float*  Csh   = (float*)(ring0 + 1024);
    float*  Dsh   = Csh + 8;

    const int mat     = blockIdx.x >> 4;
    const int colbase = (blockIdx.x & 15) << 5;
    const int tid  = threadIdx.x;
    const int w    = tid >> 5;
    const int lane = tid & 31;
    const int col  = colbase + lane;

    const float4* slotf4 = (const float4*)(g_slot + mat * 262144);
    float* myc = cols + lane * RST;

    for (int r = w * 64; r < w * 64 + 64; r += 4) {
        float4 z = make_float4(0.f, 0.f, 0.f, 0.f);
        if (col >= r && col < r + 4) ((float*)&z)[col - r] = 1.0f;
        *(float4*)&myc[r] = z;
    }

    float4 pA = __ldg(&slotf4[tid]);
    float4 pB = __ldg(&slotf4[256 + tid]);

    for (int i = 0; i < 511; i++) {
        float4* rq = (float4*)(ring0 + (i & 1) * 512);
        rq[tid] = pA;
        pA = pB;
        int np = (i + 2 <= 511) ? i + 2 : 511;
        pB = __ldg(&slotf4[np * 256 + tid]);
        __syncthreads();

        const float2* ringp = ring0 + (i & 1) * 512;
        const float4* rf    = (const float4*)ringp;

        const int L  = 511 - i;
        int Lc = (((L + 7) >> 3) + 7) & ~7;
        int m0 = w * Lc;
        int m1 = m0 + Lc; if (m1 > L) m1 = L; if (m0 > L) m0 = L;

        const float A0 = myc[i];
        float Cw = 1.0f, Dw = 0.0f;

        // ---- phase 1 ----
        {
            int nfull = (m1 - m0) >> 3;
            int m = m0;
            if (nfull > 0) {
                int j = 511 - m;
                float4 va = *(float4*)&myc[j - 3];
                float4 vb = *(float4*)&myc[j - 7];
                float4 r0 = rf[(m >> 1) + 0], r1 = rf[(m >> 1) + 1];
                float4 r2 = rf[(m >> 1) + 2], r3 = rf[(m >> 1) + 3];
                for (int g = 0; g < nfull; g++) {
                    float4 nva = va, nvb = vb, n0 = r0, n1 = r1, n2 = r2, n3 = r3;
                    if (g + 1 < nfull) {
                        int mn = m + 8, jn = 511 - mn;
                        n0 = rf[(mn >> 1) + 0]; n1 = rf[(mn >> 1) + 1];
                        n2 = rf[(mn >> 1) + 2]; n3 = rf[(mn >> 1) + 3];
                        nva = *(float4*)&myc[jn - 3];
                        nvb = *(float4*)&myc[jn - 7];
                    }
                    P1STEP(va.w, r0.x, r0.y);  P1STEP(va.z, r0.z, r0.w);
                    P1STEP(va.y, r1.x, r1.y);  P1STEP(va.x, r1.z, r1.w);
                    P1STEP(vb.w, r2.x, r2.y);  P1STEP(vb.z, r2.z, r2.w);
                    P1STEP(vb.y, r3.x, r3.y);  P1STEP(vb.x, r3.z, r3.w);
                    va = nva; vb = nvb; r0 = n0; r1 = n1; r2 = n2; r3 = n3;
                    m += 8;
                }
            }
            for (; m < m1; m++) {
                float2 p = ringp[m];
                float  u = myc[511 - m];
                Dw = fmaf(p.x, Dw, p.y * u);
                Cw = p.x * Cw;
            }
        }

        // ---- stitch ----
        if (lane == 0) Csh[w] = Cw;
        Dsh[w * 32 + lane] = Dw;
        __syncthreads();
        float A = A0;
        #pragma unroll 7
        for (int kk = 0; kk < w; kk++)
            A = fmaf(Csh[kk], A, -Dsh[kk * 32 + lane]);
        if (w == 7) myc[i] = fmaf(Cw, A, -Dw);

        // ---- phase 2 ----
        {
            int nfull = (m1 - m0) >> 3;
            int m = m0;
            if (nfull > 0) {
                int j = 511 - m;
                float4 va = *(float4*)&myc[j - 3];
                float4 vb = *(float4*)&myc[j - 7];
                float4 r0 = rf[(m >> 1) + 0], r1 = rf[(m >> 1) + 1];
                float4 r2 = rf[(m >> 1) + 2], r3 = rf[(m >> 1) + 3];
                for (int g = 0; g < nfull; g++) {
                    float4 nva = va, nvb = vb, n0 = r0, n1 = r1, n2 = r2, n3 = r3;
                    if (g + 1 < nfull) {
                        int mn = m + 8, jn = 511 - mn;
                        n0 = rf[(mn >> 1) + 0]; n1 = rf[(mn >> 1) + 1];
                        n2 = rf[(mn >> 1) + 2]; n3 = rf[(mn >> 1) + 3];
                        nva = *(float4*)&myc[jn - 3];
                        nvb = *(float4*)&myc[jn - 7];
                    }
                    P2STEP(va.w, r0.x, r0.y);  P2STEP(va.z, r0.z, r0.w);
                    P2STEP(va.y, r1.x, r1.y);  P2STEP(va.x, r1.z, r1.w);
                    P2STEP(vb.w, r2.x, r2.y);  P2STEP(vb.z, r2.z, r2.w);
                    P2STEP(vb.y, r3.x, r3.y);  P2STEP(vb.x, r3.z, r3.w);
                    int jj = 511 - m;
                    *(float4*)&myc[jj - 3] = va;
                    *(float4*)&myc[jj - 7] = vb;
                    va = nva; vb = nvb; r0 = n0; r1 = n1; r2 = n2; r3 = n3;
                    m += 8;
                }
            }
            for (; m < m1; m++) {
                float2 p = ringp[m];
                int jj = 511 - m;
                float u = myc[jj];
                float t2 = p.x * u, t1 = p.y * u;
                myc[jj] = fmaf(p.y, A, t2);
                A = fmaf(p.x, A, -t1);
            }
        }
    }
    __syncthreads();

    if (mat == 0) {
        for (int r = w * 64; r < w * 64 + 64; r++)
            g_U[r * NN + col] = __ldg(&dU[r]) * myc[r];
    } else {
        for (int r = w * 64; r < w * 64 + 64; r++)
            g_Vs[r * NN + col] = __ldg(&sigma[r]) * __ldg(&dV[r]) * myc[r];
    }
}

// ---------------- 3) W = U @ (sigma*delta_V * V) ----------------
__global__ void wgemm_kernel() {
    __shared__ float As[32][33];
    __shared__ float Bs[32][33];
    const int tx = threadIdx.x, ty = threadIdx.y;
    const int a = blockIdx.y * 32 + ty;
    const int b = blockIdx.x * 32 + tx;
    float acc = 0.0f;
    for (int kt = 0; kt < NN; kt += 32) {
        As[ty][tx] = g_U [a * NN + kt + tx];
        Bs[ty][tx] = g_Vs[(kt + ty) * NN + b];
        __syncthreads();
        #pragma unroll
        for (int kk = 0; kk < 32; kk++)
            acc += As[ty][kk] * Bs[kk][tx];
        __syncthreads();
    }
    g_W[a * NN + b] = acc;
}

// ---------------- 4) out = x @ W^T via 3-term bf16-split wmma ----------------
// out[m][n] = sum_k x[m][k] * W[n][k];  x = xh+xl, W = wh+wl (bf16 hi/lo),
// accumulate xh*wh + xh*wl + xl*wh in fp32 (lo*lo dropped, ~2^-16 relative).
#define GBK 32
#define XLD 40   // bf16 leading dim (pad vs 32 to break bank conflicts)

__global__ void __launch_bounds__(256, 2) bfgemm_kernel(const float* __restrict__ A,
                                                        float* __restrict__ C) {
    __shared__ __nv_bfloat16 xh[128][XLD], xl[128][XLD];
    __shared__ __nv_bfloat16 wh[128][XLD], wl[128][XLD];
    const float* __restrict__ Wg = g_W;

    const int tid  = threadIdx.x;
    const int warp = tid >> 5;
    const int m0 = blockIdx.y * 128;
    const int n0 = blockIdx.x * 128;

    const int wm = (warp >> 2) * 64;   // 2 warps in m -> 4 x 16 rows
    const int wn = (warp & 3) * 32;    // 4 warps in n -> 2 x 16 cols

    wmma::fragment<wmma::accumulator, 16, 16, 16, float> acc[4][2];
    #pragma unroll
    for (int i = 0; i < 4; i++)
        #pragma unroll
        for (int j = 0; j < 2; j++) wmma::fill_fragment(acc[i][j], 0.0f);

    // loader mapping: 2 threads per row, each covers 16 contiguous floats
    const int lr = tid >> 1;            // 0..127
    const int lc = (tid & 1) * 16;      // 0 or 16
    const float* Ap = A  + (size_t)(m0 + lr) * NN + lc;
    const float* Wp = Wg + (size_t)(n0 + lr) * NN + lc;

    for (int k0 = 0; k0 < NN; k0 += GBK) {
        #pragma unroll
        for (int q = 0; q < 4; q++) {
            float4 v = *(const float4*)(Ap + k0 + q * 4);
            #pragma unroll
            for (int e = 0; e < 4; e++) {
                float f = ((const float*)&v)[e];
                __nv_bfloat16 h = __float2bfloat16_rn(f);
                xh[lr][lc + q * 4 + e] = h;
                xl[lr][lc + q * 4 + e] = __float2bfloat16_rn(f - __bfloat162float(h));
            }
            float4 u = *(const float4*)(Wp + k0 + q * 4);
            #pragma unroll
            for (int e = 0; e < 4; e++) {
                float f = ((const float*)&u)[e];
                __nv_bfloat16 h = __float2bfloat16_rn(f);
                wh[lr][lc + q * 4 + e] = h;
                wl[lr][lc + q * 4 + e] = __float2bfloat16_rn(f - __bfloat162float(h));
            }
        }
        __syncthreads();

        #pragma unroll
        for (int ks = 0; ks < GBK; ks += 16) {
            wmma::fragment<wmma::matrix_a, 16, 16, 16, __nv_bfloat16, wmma::row_major> ah[4], al[4];
            wmma::fragment<wmma::matrix_b, 16, 16, 16, __nv_bfloat16, wmma::col_major> bh[2], bl[2];
            #pragma unroll
            for (int i = 0; i < 4; i++) {
                wmma::load_matrix_sync(ah[i], &xh[wm + i * 16][ks], XLD);
                wmma::load_matrix_sync(al[i], &xl[wm + i * 16][ks], XLD);
            }
            #pragma unroll
            for (int j = 0; j < 2; j++) {
                wmma::load_matrix_sync(bh[j], &wh[wn + j * 16][ks], XLD);
                wmma::load_matrix_sync(bl[j], &wl[wn + j * 16][ks], XLD);
            }
            #pragma unroll
            for (int i = 0; i < 4; i++)
                #pragma unroll
                for (int j = 0; j < 2; j++) {
                    wmma::mma_sync(acc[i][j], ah[i], bh[j], acc[i][j]);
                    wmma::mma_sync(acc[i][j], ah[i], bl[j], acc[i][j]);
                    wmma::mma_sync(acc[i][j], al[i], bh[j], acc[i][j]);
                }
        }
        __syncthreads();
    }

    #pragma unroll
    for (int i = 0; i < 4; i++)
        #pragma unroll
        for (int j = 0; j < 2; j++)
            wmma::store_matrix_sync(&C[(size_t)(m0 + wm + i * 16) * NN + n0 + wn + j * 16],
                                    acc[i][j], NN, wmma::mem_row_major);
}

// ---------------- launch ----------------
extern "C" void kernel_launch(void* const* d_in, const int* in_sizes, int n_in,
                              void* d_out, int out_size) {
    const float* x     = (const float*)d_in[0];
    const float* phiU  = (const float*)d_in[1];
    const float* dU    = (const float*)d_in[2];
    const float* phiV  = (const float*)d_in[3];
    const float* dV    = (const float*)d_in[4];
    const float* sigma = (const float*)d_in[5];
    float* out = (float*)d_out;

    const int recon_smem = 32 * RST * 4 + 1024 * 8 + (8 + 256) * 4;
    cudaFuncSetAttribute(reconstruct_kernel,
                         cudaFuncAttributeMaxDynamicSharedMemorySize, recon_smem);

    setup_cs_kernel<<<(2 * 512 * 512 + 255) / 256, 256>>>(phiU, phiV);
    reconstruct_kernel<<<32, 256, recon_smem>>>(dU, dV, sigma);
    wgemm_kernel<<<dim3(16, 16), dim3(32, 32)>>>();
    bfgemm_kernel<<<dim3(NN / 128, 32768 / 128), 256>>>(x, out);
}

// round 8
// speedup vs baseline: 1.5608x; 1.5608x over previous
#include <cuda_runtime.h>
#include <cuda_bf16.h>
#include <mma.h>
#include <cstdint>
using namespace nvcuda;

#define NN 512
#define RST 516

// ---------------- device scratch (no allocations allowed) ----------------
__device__ __align__(16) float2 g_slot[2 * 512 * 512];   // 4 MB
__device__ float g_U [NN * NN];
__device__ float g_Vs[NN * NN];
__device__ __align__(16) __nv_bfloat16 g_xhi[32768 * 512];   // 32 MB
__device__ __align__(16) __nv_bfloat16 g_xlo[32768 * 512];   // 32 MB
__device__ __align__(16) __nv_bfloat16 g_whi[NN * NN];
__device__ __align__(16) __nv_bfloat16 g_wlo[NN * NN];

__device__ __forceinline__ uint32_t smem_u32(const void* p) {
    uint32_t a;
    asm("{ .reg .u64 t; cvta.to.shared.u64 t, %1; cvt.u32.u64 %0, t; }" : "=r"(a) : "l"(p));
    return a;
}
#define CP_ASYNC16(sa, gp) \
    asm volatile("cp.async.ca.shared.global [%0], [%1], 16;" :: "r"(sa), "l"(gp) : "memory")
#define CP_COMMIT() asm volatile("cp.async.commit_group;" ::: "memory")
#define CP_WAIT(n)  asm volatile("cp.async.wait_group %0;" :: "n"(n) : "memory")

// ---------------- 1) cos/sin precompute into padded slots ----------------
__global__ void setup_cs_kernel(const float* __restrict__ phiU,
                                const float* __restrict__ phiV) {
    int tid = blockIdx.x * blockDim.x + threadIdx.x;
    if (tid >= 2 * 512 * 512) return;
    int mat = tid >> 18;
    int r   = tid & 262143;
    int i   = r >> 9;
    int m   = r & 511;
    float c = 1.0f, s = 0.0f;
    if (m < 511 - i) {
        int k = i * 511 - (i * (i - 1)) / 2 + m;
        float ph = mat ? __ldg(&phiV[k]) : __ldg(&phiU[k]);
        sincosf(ph, &s, &c);
    }
    g_slot[tid] = make_float2(c, s);
}

// ---------------- 1b) split x into bf16 hi/lo (one pass) ----------------
__global__ void xsplit_kernel(const float* __restrict__ x) {
    int i = (blockIdx.x * 256 + threadIdx.x) * 8;
    float4 v0 = *(const float4*)(x + i);
    float4 v1 = *(const float4*)(x + i + 4);
    __nv_bfloat16 h[8], l[8];
    const float* vv = (const float*)&v0;
    #pragma unroll
    for (int e = 0; e < 8; e++) {
        float f = (e < 4) ? vv[e] : ((const float*)&v1)[e - 4];
        h[e] = __float2bfloat16_rn(f);
        l[e] = __float2bfloat16_rn(f - __bfloat162float(h[e]));
    }
    *(uint4*)(g_xhi + i) = *(uint4*)h;
    *(uint4*)(g_xlo + i) = *(uint4*)l;
}

// ---------------- 2) Givens-mesh reconstruction, 8-warp chain-split ----------------
#define P2STEP(u, cc, ss) do { float _t2 = (cc)*(u); float _t1 = (ss)*(u); \
                               (u) = fmaf((ss), A, _t2); A = fmaf((cc), A, -_t1); } while (0)
#define P1STEP(u, cc, ss) do { Dw = fmaf((cc), Dw, (ss)*(u)); Cw = (cc)*Cw; } while (0)

__global__ void __launch_bounds__(256) reconstruct_kernel(const float* __restrict__ dU,
                                                          const float* __restrict__ dV,
                                                          const float* __restrict__ sigma) {
    extern __shared__ float sm[];
    float*  cols  = sm;
    float2* ring0 = (float2*)(sm + 32 * RST);
    float*  Csh   = (float*)(ring0 + 1024);
    float*  Dsh   = Csh + 8;

    const int mat     = blockIdx.x >> 4;
    const int colbase = (blockIdx.x & 15) << 5;
    const int tid  = threadIdx.x;
    const int w    = tid >> 5;
    const int lane = tid & 31;
    const int col  = colbase + lane;

    const float4* slotf4 = (const float4*)(g_slot + mat * 262144);
    float* myc = cols + lane * RST;

    for (int r = w * 64; r < w * 64 + 64; r += 4) {
        float4 z = make_float4(0.f, 0.f, 0.f, 0.f);
        if (col >= r && col < r + 4) ((float*)&z)[col - r] = 1.0f;
        *(float4*)&myc[r] = z;
    }

    float4 pA = __ldg(&slotf4[tid]);
    float4 pB = __ldg(&slotf4[256 + tid]);

    for (int i = 0; i < 511; i++) {
        float4* rq = (float4*)(ring0 + (i & 1) * 512);
        rq[tid] = pA;
        pA = pB;
        int np = (i + 2 <= 511) ? i + 2 : 511;
        pB = __ldg(&slotf4[np * 256 + tid]);
        __syncthreads();

        const float2* ringp = ring0 + (i & 1) * 512;
        const float4* rf    = (const float4*)ringp;

        const int L  = 511 - i;
        int Lc = (((L + 7) >> 3) + 7) & ~7;
        int m0 = w * Lc;
        int m1 = m0 + Lc; if (m1 > L) m1 = L; if (m0 > L) m0 = L;

        const float A0 = myc[i];
        float Cw = 1.0f, Dw = 0.0f;

        // ---- phase 1 ----
        {
            int nfull = (m1 - m0) >> 3;
            int m = m0;
            if (nfull > 0) {
                int j = 511 - m;
                float4 va = *(float4*)&myc[j - 3];
                float4 vb = *(float4*)&myc[j - 7];
                float4 r0 = rf[(m >> 1) + 0], r1 = rf[(m >> 1) + 1];
                float4 r2 = rf[(m >> 1) + 2], r3 = rf[(m >> 1) + 3];
                for (int g = 0; g < nfull; g++) {
                    float4 nva = va, nvb = vb, n0 = r0, n1 = r1, n2 = r2, n3 = r3;
                    if (g + 1 < nfull) {
                        int mn = m + 8, jn = 511 - mn;
                        n0 = rf[(mn >> 1) + 0]; n1 = rf[(mn >> 1) + 1];
                        n2 = rf[(mn >> 1) + 2]; n3 = rf[(mn >> 1) + 3];
                        nva = *(float4*)&myc[jn - 3];
                        nvb = *(float4*)&myc[jn - 7];
                    }
                    P1STEP(va.w, r0.x, r0.y);  P1STEP(va.z, r0.z, r0.w);
                    P1STEP(va.y, r1.x, r1.y);  P1STEP(va.x, r1.z, r1.w);
                    P1STEP(vb.w, r2.x, r2.y);  P1STEP(vb.z, r2.z, r2.w);
                    P1STEP(vb.y, r3.x, r3.y);  P1STEP(vb.x, r3.z, r3.w);
                    va = nva; vb = nvb; r0 = n0; r1 = n1; r2 = n2; r3 = n3;
                    m += 8;
                }
            }
            for (; m < m1; m++) {
                float2 p = ringp[m];
                float  u = myc[511 - m];
                Dw = fmaf(p.x, Dw, p.y * u);
                Cw = p.x * Cw;
            }
        }

        // ---- stitch ----
        if (lane == 0) Csh[w] = Cw;
        Dsh[w * 32 + lane] = Dw;
        __syncthreads();
        float A = A0;
        #pragma unroll 7
        for (int kk = 0; kk < w; kk++)
            A = fmaf(Csh[kk], A, -Dsh[kk * 32 + lane]);
        if (w == 7) myc[i] = fmaf(Cw, A, -Dw);

        // ---- phase 2 ----
        {
            int nfull = (m1 - m0) >> 3;
            int m = m0;
            if (nfull > 0) {
                int j = 511 - m;
                float4 va = *(float4*)&myc[j - 3];
                float4 vb = *(float4*)&myc[j - 7];
                float4 r0 = rf[(m >> 1) + 0], r1 = rf[(m >> 1) + 1];
                float4 r2 = rf[(m >> 1) + 2], r3 = rf[(m >> 1) + 3];
                for (int g = 0; g < nfull; g++) {
                    float4 nva = va, nvb = vb, n0 = r0, n1 = r1, n2 = r2, n3 = r3;
                    if (g + 1 < nfull) {
                        int mn = m + 8, jn = 511 - mn;
                        n0 = rf[(mn >> 1) + 0]; n1 = rf[(mn >> 1) + 1];
                        n2 = rf[(mn >> 1) + 2]; n3 = rf[(mn >> 1) + 3];
                        nva = *(float4*)&myc[jn - 3];
                        nvb = *(float4*)&myc[jn - 7];
                    }
                    P2STEP(va.w, r0.x, r0.y);  P2STEP(va.z, r0.z, r0.w);
                    P2STEP(va.y, r1.x, r1.y);  P2STEP(va.x, r1.z, r1.w);
                    P2STEP(vb.w, r2.x, r2.y);  P2STEP(vb.z, r2.z, r2.w);
                    P2STEP(vb.y, r3.x, r3.y);  P2STEP(vb.x, r3.z, r3.w);
                    int jj = 511 - m;
                    *(float4*)&myc[jj - 3] = va;
                    *(float4*)&myc[jj - 7] = vb;
                    va = nva; vb = nvb; r0 = n0; r1 = n1; r2 = n2; r3 = n3;
                    m += 8;
                }
            }
            for (; m < m1; m++) {
                float2 p = ringp[m];
                int jj = 511 - m;
                float u = myc[jj];
                float t2 = p.x * u, t1 = p.y * u;
                myc[jj] = fmaf(p.y, A, t2);
                A = fmaf(p.x, A, -t1);
            }
        }
    }
    __syncthreads();

    if (mat == 0) {
        for (int r = w * 64; r < w * 64 + 64; r++)
            g_U[r * NN + col] = __ldg(&dU[r]) * myc[r];
    } else {
        for (int r = w * 64; r < w * 64 + 64; r++)
            g_Vs[r * NN + col] = __ldg(&sigma[r]) * __ldg(&dV[r]) * myc[r];
    }
}

// ---------------- 3) W = U @ (sigma*delta_V * V), bf16 hi/lo output ----------------
__global__ void wgemm_kernel() {
    __shared__ float As[32][33];
    __shared__ float Bs[32][33];
    const int tx = threadIdx.x, ty = threadIdx.y;
    const int a = blockIdx.y * 32 + ty;
    const int b = blockIdx.x * 32 + tx;
    float acc = 0.0f;
    for (int kt = 0; kt < NN; kt += 32) {
        As[ty][tx] = g_U [a * NN + kt + tx];
        Bs[ty][tx] = g_Vs[(kt + ty) * NN + b];
        __syncthreads();
        #pragma unroll
        for (int kk = 0; kk < 32; kk++)
            acc += As[ty][kk] * Bs[kk][tx];
        __syncthreads();
    }
    __nv_bfloat16 hi = __float2bfloat16_rn(acc);
    g_whi[a * NN + b] = hi;
    g_wlo[a * NN + b] = __float2bfloat16_rn(acc - __bfloat162float(hi));
}

// ---------------- 4) out = x @ W^T, 3-term bf16 wmma, cp.async pipeline ----------------
#define GBK 32
#define XLD 40                       // bf16 leading dim (80 B row stride)
#define TILE_H (128 * XLD)           // halves per tile
#define STAGE_H (4 * TILE_H)         // xh, xl, wh, wl

__global__ void __launch_bounds__(256, 2) bfgemm_kernel(float* __restrict__ C) {
    __shared__ __nv_bfloat16 sbuf[2 * STAGE_H];

    const int tid  = threadIdx.x;
    const int warp = tid >> 5;
    const int m0 = blockIdx.y * 128;
    const int n0 = blockIdx.x * 128;
    const int wm = (warp >> 2) * 64;
    const int wn = (warp & 3) * 32;

    wmma::fragment<wmma::accumulator, 16, 16, 16, float> acc[4][2];
    #pragma unroll
    for (int i = 0; i < 4; i++)
        #pragma unroll
        for (int j = 0; j < 2; j++) wmma::fill_fragment(acc[i][j], 0.0f);

    // copy mapping: row = tid>>1 (0..127), half = (tid&1)*16 elements, 2x16B per tile
    const int lr = tid >> 1;
    const int lh = (tid & 1) * 16;
    const __nv_bfloat16* gx[4];
    gx[0] = g_xhi + (size_t)(m0 + lr) * NN + lh;
    gx[1] = g_xlo + (size_t)(m0 + lr) * NN + lh;
    gx[2] = g_whi + (size_t)(n0 + lr) * NN + lh;
    gx[3] = g_wlo + (size_t)(n0 + lr) * NN + lh;
    const uint32_t sb0 = smem_u32(sbuf);
    const uint32_t dst_row = (uint32_t)(lr * XLD + lh) * 2;   // byte offset in tile

    #define COPY_TILE(t, stg) do { \
        uint32_t _b = sb0 + (stg) * (STAGE_H * 2); \
        int _k = (t) * GBK; \
        _Pragma("unroll") \
        for (int _p = 0; _p < 4; _p++) { \
            uint32_t _d = _b + _p * (TILE_H * 2) + dst_row; \
            CP_ASYNC16(_d,      gx[_p] + _k); \
            CP_ASYNC16(_d + 16, gx[_p] + _k + 8); \
        } } while (0)

    COPY_TILE(0, 0);
    CP_COMMIT();

    for (int t = 0; t < NN / GBK; t++) {
        const int cur = t & 1;
        if (t + 1 < NN / GBK) { COPY_TILE(t + 1, cur ^ 1); CP_COMMIT(); CP_WAIT(1); }
        else                  { CP_WAIT(0); }
        __syncthreads();

        const __nv_bfloat16* xh = sbuf + cur * STAGE_H;
        const __nv_bfloat16* xl = xh + TILE_H;
        const __nv_bfloat16* wh = xl + TILE_H;
        const __nv_bfloat16* wl = wh + TILE_H;

        #pragma unroll
        for (int ks = 0; ks < GBK; ks += 16) {
            wmma::fragment<wmma::matrix_a, 16, 16, 16, __nv_bfloat16, wmma::row_major> ah[4], al[4];
            wmma::fragment<wmma::matrix_b, 16, 16, 16, __nv_bfloat16, wmma::col_major> bh[2], bl[2];
            #pragma unroll
            for (int i = 0; i < 4; i++) {
                wmma::load_matrix_sync(ah[i], xh + (wm + i * 16) * XLD + ks, XLD);
                wmma::load_matrix_sync(al[i], xl + (wm + i * 16) * XLD + ks, XLD);
            }
            #pragma unroll
            for (int j = 0; j < 2; j++) {
                wmma::load_matrix_sync(bh[j], wh + (wn + j * 16) * XLD + ks, XLD);
                wmma::load_matrix_sync(bl[j], wl + (wn + j * 16) * XLD + ks, XLD);
            }
            #pragma unroll
            for (int i = 0; i < 4; i++)
                #pragma unroll
                for (int j = 0; j < 2; j++) {
                    wmma::mma_sync(acc[i][j], ah[i], bh[j], acc[i][j]);
                    wmma::mma_sync(acc[i][j], ah[i], bl[j], acc[i][j]);
                    wmma::mma_sync(acc[i][j], al[i], bh[j], acc[i][j]);
                }
        }
        __syncthreads();
    }

    #pragma unroll
    for (int i = 0; i < 4; i++)
        #pragma unroll
        for (int j = 0; j < 2; j++)
            wmma::store_matrix_sync(&C[(size_t)(m0 + wm + i * 16) * NN + n0 + wn + j * 16],
                                    acc[i][j], NN, wmma::mem_row_major);
}

// ---------------- launch ----------------
extern "C" void kernel_launch(void* const* d_in, const int* in_sizes, int n_in,
                              void* d_out, int out_size) {
    const float* x     = (const float*)d_in[0];
    const float* phiU  = (const float*)d_in[1];
    const float* dU    = (const float*)d_in[2];
    const float* phiV  = (const float*)d_in[3];
    const float* dV    = (const float*)d_in[4];
    const float* sigma = (const float*)d_in[5];
    float* out = (float*)d_out;

    const int recon_smem = 32 * RST * 4 + 1024 * 8 + (8 + 256) * 4;
    cudaFuncSetAttribute(reconstruct_kernel,
                         cudaFuncAttributeMaxDynamicSharedMemorySize, recon_smem);

    setup_cs_kernel<<<(2 * 512 * 512 + 255) / 256, 256>>>(phiU, phiV);
    xsplit_kernel<<<32768 * 512 / (256 * 8), 256>>>(x);
    reconstruct_kernel<<<32, 256, recon_smem>>>(dU, dV, sigma);
    wgemm_kernel<<<dim3(16, 16), dim3(32, 32)>>>();
    bfgemm_kernel<<<dim3(NN / 128, 32768 / 128), 256>>>(out);
}

// round 10
// speedup vs baseline: 1.6797x; 1.0762x over previous
#include <cuda_runtime.h>
#include <cuda_bf16.h>
#include <mma.h>
#include <cstdint>
using namespace nvcuda;

#define NN 512
#define RST 516

// ---------------- device scratch (no allocations allowed) ----------------
__device__ __align__(16) float2 g_slot[2 * 512 * 512];   // 4 MB
__device__ float g_U [NN * NN];
__device__ float g_Vs[NN * NN];
__device__ __align__(16) __nv_bfloat16 g_xhi[32768 * 512];   // 32 MB
__device__ __align__(16) __nv_bfloat16 g_xlo[32768 * 512];   // 32 MB
__device__ __align__(16) __nv_bfloat16 g_whi[NN * NN];
__device__ __align__(16) __nv_bfloat16 g_wlo[NN * NN];

__device__ __forceinline__ uint32_t smem_u32(const void* p) {
    uint32_t a;
    asm("{ .reg .u64 t; cvta.to.shared.u64 t, %1; cvt.u32.u64 %0, t; }" : "=r"(a) : "l"(p));
    return a;
}
#define CP_ASYNC16(sa, gp) \
    asm volatile("cp.async.ca.shared.global [%0], [%1], 16;" :: "r"(sa), "l"(gp) : "memory")
#define CP_COMMIT() asm volatile("cp.async.commit_group;" ::: "memory")
#define CP_WAIT(n)  asm volatile("cp.async.wait_group %0;" :: "n"(n) : "memory")

// ---------------- 1) cos/sin precompute into padded slots ----------------
__global__ void setup_cs_kernel(const float* __restrict__ phiU,
                                const float* __restrict__ phiV) {
    int tid = blockIdx.x * blockDim.x + threadIdx.x;
    if (tid >= 2 * 512 * 512) return;
    int mat = tid >> 18;
    int r   = tid & 262143;
    int i   = r >> 9;
    int m   = r & 511;
    float c = 1.0f, s = 0.0f;
    if (m < 511 - i) {
        int k = i * 511 - (i * (i - 1)) / 2 + m;
        float ph = mat ? __ldg(&phiV[k]) : __ldg(&phiU[k]);
        sincosf(ph, &s, &c);
    }
    g_slot[tid] = make_float2(c, s);
}

// ---------------- 1b) split x into bf16 hi/lo (one pass) ----------------
__global__ void xsplit_kernel(const float* __restrict__ x) {
    int i = (blockIdx.x * 256 + threadIdx.x) * 8;
    float4 v0 = *(const float4*)(x + i);
    float4 v1 = *(const float4*)(x + i + 4);
    __nv_bfloat16 h[8], l[8];
    const float* vv = (const float*)&v0;
    #pragma unroll
    for (int e = 0; e < 8; e++) {
        float f = (e < 4) ? vv[e] : ((const float*)&v1)[e - 4];
        h[e] = __float2bfloat16_rn(f);
        l[e] = __float2bfloat16_rn(f - __bfloat162float(h[e]));
    }
    *(uint4*)(g_xhi + i) = *(uint4*)h;
    *(uint4*)(g_xlo + i) = *(uint4*)l;
}

// ---------------- 2) Givens-mesh reconstruction, 1-barrier pivots ----------------
// 8 warps; lane owns a column (smem). Warp w owns rotation range
// m in [w*Lc, min((w+1)*Lc, L)) (warp 7 takes the tail), Lc fixed per 64-pivot
// block. Since m <-> row j=511-m is pivot-independent, warp w's phase1(i+1)
// reads only rows its own phase2(i) wrote -> ONE __syncthreads per pivot
// (the stitch). cs slices are per-warp self-staged into a parity ring;
// A0 (pivot row value) is broadcast via a parity smem slot staged by the
// owning warp before the barrier.
// Staging invariant at top of pivot i: ring[par]=slice(i), pf=slice(i+1),
// pf2=slice(i+2); in-loop we stage pf and refill pf2 from slice(i+3).
#define P2STEP(u, cc, ss) do { float _t2 = (cc)*(u); float _t1 = (ss)*(u); \
                               (u) = fmaf((ss), A, _t2); A = fmaf((cc), A, -_t1); } while (0)
#define P1STEP(u, cc, ss) do { Dw = fmaf((cc), Dw, (ss)*(u)); Cw = (cc)*Cw; } while (0)

__global__ void __launch_bounds__(256) reconstruct_kernel(const float* __restrict__ dU,
                                                          const float* __restrict__ dV,
                                                          const float* __restrict__ sigma) {
    extern __shared__ float sm[];
    float*  cols  = sm;                               // 32*RST floats
    float2* ring0 = (float2*)(sm + 32 * RST);         // 2 x 512 float2
    float*  Csh   = (float*)(ring0 + 1024);           // 2 x 8
    float*  Dsh   = Csh + 16;                         // 2 x 8 x 32
    float*  A0sh  = Dsh + 512;                        // 2 x 32

    const int mat     = blockIdx.x >> 4;
    const int colbase = (blockIdx.x & 15) << 5;
    const int tid  = threadIdx.x;
    const int w    = tid >> 5;
    const int lane = tid & 31;
    const int col  = colbase + lane;

    const float4* slotf4 = (const float4*)(g_slot + mat * 262144);  // 256 f4/pivot
    float* myc = cols + lane * RST;

    // identity columns
    for (int r = w * 64; r < w * 64 + 64; r += 4) {
        float4 z = make_float4(0.f, 0.f, 0.f, 0.f);
        if (col >= r && col < r + 4) ((float*)&z)[col - r] = 1.0f;
        *(float4*)&myc[r] = z;
    }

    for (int B = 0; B < 511; B += 64) {
        const int Bend = (B + 64 < 511) ? B + 64 : 511;
        const int LB = 511 - B;
        const int Lc = ((LB + 63) >> 6) << 3;        // per-warp chunk, mult of 8, <=64
        const int m0 = w * Lc;
        const int f40 = m0 >> 1;                     // slice start in float4
        const int nf4 = (w == 7) ? 32 : (Lc >> 1);   // slice float4 count (<=32)
        const bool lact = (lane < nf4) && (f40 + lane < 256);

        __syncthreads();                             // block barrier

        // stage A0 for the first pivot of the block
        if (w == 7) A0sh[(B & 1) * 32 + lane] = myc[B];

        // prime cs: stage slice(B), prefetch slice(B+1), issue slice(B+2)
        float4 pf, pf2;
        {
            float4* rw = (float4*)(ring0 + (B & 1) * 512);
            if (lact) {
                float4 s0 = __ldg(slotf4 + B * 256 + f40 + lane);
                rw[f40 + lane] = s0;
                int i1 = (B + 1 <= 510) ? B + 1 : 510;
                int i2 = (B + 2 <= 510) ? B + 2 : 510;
                pf  = __ldg(slotf4 + i1 * 256 + f40 + lane);
                pf2 = __ldg(slotf4 + i2 * 256 + f40 + lane);
            }
            __syncwarp();
        }

        for (int i = B; i < Bend; i++) {
            const int par = i & 1;
            const int L = 511 - i;
            const int mm0 = (m0 < L) ? m0 : L;
            const int m1  = (w == 7) ? L : ((m0 + Lc < L) ? m0 + Lc : L);

            const float2* ringp = ring0 + par * 512;
            const float4* rf    = (const float4*)ringp;

            // stage A0 for THIS pivot (owner warp; i==B handled at prime)
            if (i > B) {
                int wown = L / Lc; if (wown > 7) wown = 7;
                if (w == wown) A0sh[par * 32 + lane] = myc[i];
            }

            float Cw = 1.0f, Dw = 0.0f;

            // ---- phase 1: (C, D) over own slice ----
            {
                int nfull = (m1 - mm0) >> 3;
                int m = mm0;
                if (nfull > 0) {
                    int j = 511 - m;
                    float4 va = *(float4*)&myc[j - 3];
                    float4 vb = *(float4*)&myc[j - 7];
                    float4 r0 = rf[(m >> 1) + 0], r1 = rf[(m >> 1) + 1];
                    float4 r2 = rf[(m >> 1) + 2], r3 = rf[(m >> 1) + 3];
                    for (int g = 0; g < nfull; g++) {
                        float4 nva = va, nvb = vb, n0 = r0, n1 = r1, n2 = r2, n3 = r3;
                        if (g + 1 < nfull) {
                            int mn = m + 8, jn = 511 - mn;
                            n0 = rf[(mn >> 1) + 0]; n1 = rf[(mn >> 1) + 1];
                            n2 = rf[(mn >> 1) + 2]; n3 = rf[(mn >> 1) + 3];
                            nva = *(float4*)&myc[jn - 3];
                            nvb = *(float4*)&myc[jn - 7];
                        }
                        P1STEP(va.w, r0.x, r0.y);  P1STEP(va.z, r0.z, r0.w);
                        P1STEP(va.y, r1.x, r1.y);  P1STEP(va.x, r1.z, r1.w);
                        P1STEP(vb.w, r2.x, r2.y);  P1STEP(vb.z, r2.z, r2.w);
                        P1STEP(vb.y, r3.x, r3.y);  P1STEP(vb.x, r3.z, r3.w);
                        va = nva; vb = nvb; r0 = n0; r1 = n1; r2 = n2; r3 = n3;
                        m += 8;
                    }
                }
                for (; m < m1; m++) {
                    float2 p = ringp[m];
                    float  u = myc[511 - m];
                    Dw = fmaf(p.x, Dw, p.y * u);
                    Cw = p.x * Cw;
                }
            }

            if (lane == 0) Csh[par * 8 + w] = Cw;
            Dsh[par * 256 + w * 32 + lane] = Dw;

            // stage next pivot's cs slice; refill pf2 from slice(i+3)
            if (i + 1 < Bend) {
                __syncwarp();          // own phase2(i-1) reads of parity^1 done
                float4* rw = (float4*)(ring0 + (par ^ 1) * 512);
                if (lact) {
                    rw[f40 + lane] = pf;
                    pf = pf2;
                    int nx = (i + 3 <= 510) ? i + 3 : 510;
                    pf2 = __ldg(slotf4 + nx * 256 + f40 + lane);
                }
            }

            __syncthreads();           // the one barrier: stitch

            // fold incoming A
            float A = A0sh[par * 32 + lane];
            #pragma unroll 7
            for (int kk = 0; kk < w; kk++)
                A = fmaf(Csh[par * 8 + kk], A, -Dsh[par * 256 + kk * 32 + lane]);
            if (w == 7) myc[i] = fmaf(Cw, A, -Dw);   // final pivot value

            // ---- phase 2: replay own slice ----
            {
                int nfull = (m1 - mm0) >> 3;
                int m = mm0;
                if (nfull > 0) {
                    int j = 511 - m;
                    float4 va = *(float4*)&myc[j - 3];
                    float4 vb = *(float4*)&myc[j - 7];
                    float4 r0 = rf[(m >> 1) + 0], r1 = rf[(m >> 1) + 1];
                    float4 r2 = rf[(m >> 1) + 2], r3 = rf[(m >> 1) + 3];
                    for (int g = 0; g < nfull; g++) {
                        float4 nva = va, nvb = vb, n0 = r0, n1 = r1, n2 = r2, n3 = r3;
                        if (g + 1 < nfull) {
                            int mn = m + 8, jn = 511 - mn;
                            n0 = rf[(mn >> 1) + 0]; n1 = rf[(mn >> 1) + 1];
                            n2 = rf[(mn >> 1) + 2]; n3 = rf[(mn >> 1) + 3];
                            nva = *(float4*)&myc[jn - 3];
                            nvb = *(float4*)&myc[jn - 7];
                        }
                        P2STEP(va.w, r0.x, r0.y);  P2STEP(va.z, r0.z, r0.w);
                        P2STEP(va.y, r1.x, r1.y);  P2STEP(va.x, r1.z, r1.w);
                        P2STEP(vb.w, r2.x, r2.y);  P2STEP(vb.z, r2.z, r2.w);
                        P2STEP(vb.y, r3.x, r3.y);  P2STEP(vb.x, r3.z, r3.w);
                        int jj = 511 - m;
                        *(float4*)&myc[jj - 3] = va;
                        *(float4*)&myc[jj - 7] = vb;
                        va = nva; vb = nvb; r0 = n0; r1 = n1; r2 = n2; r3 = n3;
                        m += 8;
                    }
                }
                for (; m < m1; m++) {
                    float2 p = ringp[m];
                    int jj = 511 - m;
                    float u = myc[jj];
                    float t2 = p.x * u, t1 = p.y * u;
                    myc[jj] = fmaf(p.y, A, t2);
                    A = fmaf(p.x, A, -t1);
                }
            }
        }
    }
    __syncthreads();

    // writeback: warp w rows [w*64, w*64+64), coalesced across lanes
    if (mat == 0) {
        for (int r = w * 64; r < w * 64 + 64; r++)
            g_U[r * NN + col] = __ldg(&dU[r]) * myc[r];
    } else {
        for (int r = w * 64; r < w * 64 + 64; r++)
            g_Vs[r * NN + col] = __ldg(&sigma[r]) * __ldg(&dV[r]) * myc[r];
    }
}

// ---------------- 3) W = U @ (sigma*delta_V * V), bf16 hi/lo output ----------------
__global__ void wgemm_kernel() {
    __shared__ float As[32][33];
    __shared__ float Bs[32][33];
    const int tx = threadIdx.x, ty = threadIdx.y;
    const int a = blockIdx.y * 32 + ty;
    const int b = blockIdx.x * 32 + tx;
    float acc = 0.0f;
    for (int kt = 0; kt < NN; kt += 32) {
        As[ty][tx] = g_U [a * NN + kt + tx];
        Bs[ty][tx] = g_Vs[(kt + ty) * NN + b];
        __syncthreads();
        #pragma unroll
        for (int kk = 0; kk < 32; kk++)
            acc += As[ty][kk] * Bs[kk][tx];
        __syncthreads();
    }
    __nv_bfloat16 hi = __float2bfloat16_rn(acc);
    g_whi[a * NN + b] = hi;
    g_wlo[a * NN + b] = __float2bfloat16_rn(acc - __bfloat162float(hi));
}

// ---------------- 4) out = x @ W^T, 3-term bf16 wmma, cp.async pipeline ----------------
#define GBK 32
#define XLD 40
#define TILE_H (128 * XLD)
#define STAGE_H (4 * TILE_H)

__global__ void __launch_bounds__(256, 2) bfgemm_kernel(float* __restrict__ C) {
    __shared__ __nv_bfloat16 sbuf[2 * STAGE_H];

    const int tid  = threadIdx.x;
    const int warp = tid >> 5;
    const int m0 = blockIdx.y * 128;
    const int n0 = blockIdx.x * 128;
    const int wm = (warp >> 2) * 64;
    const int wn = (warp & 3) * 32;

    wmma::fragment<wmma::accumulator, 16, 16, 16, float> acc[4][2];
    #pragma unroll
    for (int i = 0; i < 4; i++)
        #pragma unroll
        for (int j = 0; j < 2; j++) wmma::fill_fragment(acc[i][j], 0.0f);

    const int lr = tid >> 1;
    const int lh = (tid & 1) * 16;
    const __nv_bfloat16* gx[4];
    gx[0] = g_xhi + (size_t)(m0 + lr) * NN + lh;
    gx[1] = g_xlo + (size_t)(m0 + lr) * NN + lh;
    gx[2] = g_whi + (size_t)(n0 + lr) * NN + lh;
    gx[3] = g_wlo + (size_t)(n0 + lr) * NN + lh;
    const uint32_t sb0 = smem_u32(sbuf);
    const uint32_t dst_row = (uint32_t)(lr * XLD + lh) * 2;

    #define COPY_TILE(t, stg) do { \
        uint32_t _b = sb0 + (stg) * (STAGE_H * 2); \
        int _k = (t) * GBK; \
        _Pragma("unroll") \
        for (int _p = 0; _p < 4; _p++) { \
            uint32_t _d = _b + _p * (TILE_H * 2) + dst_row; \
            CP_ASYNC16(_d,      gx[_p] + _k); \
            CP_ASYNC16(_d + 16, gx[_p] + _k + 8); \
        } } while (0)

    COPY_TILE(0, 0);
    CP_COMMIT();

    for (int t = 0; t < NN / GBK; t++) {
        const int cur = t & 1;
        if (t + 1 < NN / GBK) { COPY_TILE(t + 1, cur ^ 1); CP_COMMIT(); CP_WAIT(1); }
        else                  { CP_WAIT(0); }
        __syncthreads();

        const __nv_bfloat16* xh = sbuf + cur * STAGE_H;
        const __nv_bfloat16* xl = xh + TILE_H;
        const __nv_bfloat16* wh = xl + TILE_H;
        const __nv_bfloat16* wl = wh + TILE_H;

        #pragma unroll
        for (int ks = 0; ks < GBK; ks += 16) {
            wmma::fragment<wmma::matrix_a, 16, 16, 16, __nv_bfloat16, wmma::row_major> ah[4], al[4];
            wmma::fragment<wmma::matrix_b, 16, 16, 16, __nv_bfloat16, wmma::col_major> bh[2], bl[2];
            #pragma unroll
            for (int i = 0; i < 4; i++) {
                wmma::load_matrix_sync(ah[i], xh + (wm + i * 16) * XLD + ks, XLD);
                wmma::load_matrix_sync(al[i], xl + (wm + i * 16) * XLD + ks, XLD);
            }
            #pragma unroll
            for (int j = 0; j < 2; j++) {
                wmma::load_matrix_sync(bh[j], wh + (wn + j * 16) * XLD + ks, XLD);
                wmma::load_matrix_sync(bl[j], wl + (wn + j * 16) * XLD + ks, XLD);
            }
            #pragma unroll
            for (int i = 0; i < 4; i++)
                #pragma unroll
                for (int j = 0; j < 2; j++) {
                    wmma::mma_sync(acc[i][j], ah[i], bh[j], acc[i][j]);
                    wmma::mma_sync(acc[i][j], ah[i], bl[j], acc[i][j]);
                    wmma::mma_sync(acc[i][j], al[i], bh[j], acc[i][j]);
                }
        }
        __syncthreads();
    }

    #pragma unroll
    for (int i = 0; i < 4; i++)
        #pragma unroll
        for (int j = 0; j < 2; j++)
            wmma::store_matrix_sync(&C[(size_t)(m0 + wm + i * 16) * NN + n0 + wn + j * 16],
                                    acc[i][j], NN, wmma::mem_row_major);
}

// ---------------- launch ----------------
extern "C" void kernel_launch(void* const* d_in, const int* in_sizes, int n_in,
                              void* d_out, int out_size) {
    const float* x     = (const float*)d_in[0];
    const float* phiU  = (const float*)d_in[1];
    const float* dU    = (const float*)d_in[2];
    const float* phiV  = (const float*)d_in[3];
    const float* dV    = (const float*)d_in[4];
    const float* sigma = (const float*)d_in[5];
    float* out = (float*)d_out;

    const int recon_smem = 32 * RST * 4 + 1024 * 8 + (16 + 512 + 64) * 4;
    cudaFuncSetAttribute(reconstruct_kernel,
                         cudaFuncAttributeMaxDynamicSharedMemorySize, recon_smem);

    setup_cs_kernel<<<(2 * 512 * 512 + 255) / 256, 256>>>(phiU, phiV);
    xsplit_kernel<<<32768 * 512 / (256 * 8), 256>>>(x);
    reconstruct_kernel<<<32, 256, recon_smem>>>(dU, dV, sigma);
    wgemm_kernel<<<dim3(16, 16), dim3(32, 32)>>>();
    bfgemm_kernel<<<dim3(NN / 128, 32768 / 128), 256>>>(out);
}